// round 2
// baseline (speedup 1.0000x reference)
#include <cuda_runtime.h>
#include <math.h>

#define NN 30000
#define EE 100000
#define DD 200
#define RR 100
#define BB 50
#define OUT4 (4*DD)   // 800 packed output columns: k,q,v,s

// ---------------- scratch (static device globals; no runtime alloc) ----------------
__device__ __align__(16) float g_M[RR*DD*DD];        // per-relation matrices, 16MB
__device__ __align__(16) float g_W4[OUT4*DD];        // packed weights [800][200]
__device__ float g_b4[OUT4];
__device__ __align__(16) float g_KQVS[4u*NN*DD];     // K|Q|V|S node features, 96MB
__device__ float g_att[EE];
__device__ float g_ex[EE];
__device__ unsigned g_maxu[NN];
__device__ float g_denom[NN];
__device__ __align__(16) float g_agg[NN*DD];         // agg, then n_pre in place
__device__ int g_cnt[RR];
__device__ int g_off[RR+1];
__device__ int g_cur[RR];
__device__ int g_eid[EE];
__device__ float g_colsum[DD];
__device__ float g_colsum2[DD];
__device__ float g_scale[DD];
__device__ float g_shift[DD];

// ---------------- init ----------------
__global__ void k_init() {
  int stride = gridDim.x*blockDim.x;
  int t0 = blockIdx.x*blockDim.x + threadIdx.x;
  for (int t = t0; t < NN*DD; t += stride) g_agg[t] = 0.f;
  for (int t = t0; t < NN; t += stride) { g_maxu[t] = 0x007FFFFFu; g_denom[t] = 0.f; } // enc(-inf)
  for (int t = t0; t < RR; t += stride) { g_cnt[t] = 0; g_cur[t] = 0; }
  for (int t = t0; t < DD; t += stride) { g_colsum[t] = 0.f; g_colsum2[t] = 0.f; }
}

// ---------------- M_r = sum_b w_comp[r,b] * A_b ----------------
__global__ void k_compM(const float* __restrict__ A, const float* __restrict__ wc) {
  __shared__ float Ash[BB][DD];   // 40KB
  int i = blockIdx.x;             // row index of DxD
  int tid = threadIdx.x;
  for (int idx = tid; idx < BB*DD; idx += blockDim.x) {
    int b = idx / DD, j = idx % DD;
    Ash[b][j] = A[(size_t)b*DD*DD + (size_t)i*DD + j];
  }
  __syncthreads();
  if (tid < DD) {
    for (int r = 0; r < RR; r++) {
      float acc = 0.f;
      #pragma unroll 10
      for (int b = 0; b < BB; b++) acc = fmaf(__ldg(&wc[r*BB+b]), Ash[b][tid], acc);
      g_M[(size_t)r*DD*DD + (size_t)i*DD + tid] = acc;
    }
  }
}

// ---------------- pack weights/biases for fused KQVS GEMM ----------------
__global__ void k_pack(const float* __restrict__ kw, const float* __restrict__ qw,
                       const float* __restrict__ vw, const float* __restrict__ sw) {
  int idx = blockIdx.x*blockDim.x + threadIdx.x;
  if (idx >= OUT4*DD) return;
  int o = idx / DD, i = idx - o*DD;
  int z = o / DD, j = o - z*DD;
  const float* w = (z==0)?kw:(z==1)?qw:(z==2)?vw:sw;
  g_W4[idx] = w[(size_t)j*DD + i];
}

__global__ void k_packb(const float* __restrict__ kb, const float* __restrict__ qb,
                        const float* __restrict__ vb, const float* __restrict__ sb,
                        const float* __restrict__ loop, const float* __restrict__ sw) {
  int o = threadIdx.x;
  if (o >= OUT4) return;
  int z = o / DD, j = o - z*DD;
  float bias = (z==0)?kb[j]:(z==1)?qb[j]:(z==2)?vb[j]:sb[j];
  if (z == 3) { // fold -(loop_rel @ wS^T) into bias
    float c = 0.f;
    for (int i = 0; i < DD; i++) c = fmaf(loop[i], sw[(size_t)j*DD+i], c);
    bias -= c;
  }
  g_b4[o] = bias;
}

// ---------------- fused X @ W4^T GEMM -> K,Q,V,S ----------------
#define GBM 128
#define GBN 64
#define GBK 16
__global__ __launch_bounds__(512) void k_gemm(const float* __restrict__ X) {
  __shared__ float As[GBM][GBK+1];
  __shared__ float Bs[GBN][GBK+1];
  int row0 = blockIdx.x*GBM, col0 = blockIdx.y*GBN;
  int tid = threadIdx.x;
  int tx = tid & 15, ty = tid >> 4;
  float acc[4][4];
  #pragma unroll
  for (int u=0;u<4;u++) { acc[u][0]=0.f; acc[u][1]=0.f; acc[u][2]=0.f; acc[u][3]=0.f; }
  for (int k0 = 0; k0 < DD; k0 += GBK) {
    #pragma unroll
    for (int l = 0; l < 4; l++) {
      int idx = tid + l*512;
      int r = idx >> 4, c = idx & 15;
      int gr = row0 + r, gc = k0 + c;
      As[r][c] = (gr < NN && gc < DD) ? X[(size_t)gr*DD + gc] : 0.f;
    }
    #pragma unroll
    for (int l = 0; l < 2; l++) {
      int idx = tid + l*512;
      int r = idx >> 4, c = idx & 15;
      int go = col0 + r, gc = k0 + c;
      Bs[r][c] = (go < OUT4 && gc < DD) ? g_W4[(size_t)go*DD + gc] : 0.f;
    }
    __syncthreads();
    #pragma unroll
    for (int kk = 0; kk < GBK; kk++) {
      float a[4], b[4];
      #pragma unroll
      for (int u=0;u<4;u++) a[u] = As[ty*4+u][kk];
      #pragma unroll
      for (int v=0;v<4;v++) b[v] = Bs[tx*4+v][kk];
      #pragma unroll
      for (int u=0;u<4;u++) {
        #pragma unroll
        for (int v=0;v<4;v++) acc[u][v] = fmaf(a[u], b[v], acc[u][v]);
      }
    }
    __syncthreads();
  }
  #pragma unroll
  for (int u=0;u<4;u++) {
    int n = row0 + ty*4 + u;
    if (n >= NN) continue;
    #pragma unroll
    for (int v=0;v<4;v++) {
      int o = col0 + tx*4 + v;
      if (o >= OUT4) continue;
      int z = o / DD, j = o - z*DD;
      g_KQVS[(size_t)z*NN*DD + (size_t)n*DD + j] = acc[u][v] + g_b4[o];
    }
  }
}

// ---------------- counting sort of edges by relation ----------------
__global__ void k_hist(const int* __restrict__ et) {
  int e = blockIdx.x*blockDim.x + threadIdx.x;
  if (e < EE) atomicAdd(&g_cnt[et[e]], 1);
}
__global__ void k_scan() {
  if (threadIdx.x == 0) {
    int s = 0;
    for (int r = 0; r < RR; r++) { g_off[r] = s; s += g_cnt[r]; }
    g_off[RR] = s;
  }
}
__global__ void k_scatter(const int* __restrict__ et) {
  int e = blockIdx.x*blockDim.x + threadIdx.x;
  if (e < EE) {
    int t = et[e];
    int p = atomicAdd(&g_cur[t], 1);
    g_eid[g_off[t] + p] = e;
  }
}

// ---------------- attention: att_e = k^T M_r q, per-relation smem GEMM ----------------
#define ABM 128
#define ATT_SMEM (ABM*DD*4 + DD*64*4 + ABM*64*4 + ABM*4 + 3*ABM*4)  // 188416 B
__global__ __launch_bounds__(512, 1) void k_att(const int* __restrict__ src, const int* __restrict__ dst) {
  extern __shared__ float sm[];
  float* k_sh   = sm;                 // [ABM][DD]
  float* Msh    = k_sh + ABM*DD;      // [DD][64]
  float* q_t    = Msh + DD*64;        // [ABM][64]
  float* att_sh = q_t + ABM*64;       // [ABM]
  int* es_src = (int*)(att_sh + ABM);
  int* es_dst = es_src + ABM;
  int* es_eid = es_dst + ABM;

  int r = blockIdx.x;
  int beg = g_off[r], end = g_off[r+1];
  int base = beg + blockIdx.y*ABM;
  if (base >= end) return;
  int m = end - base; if (m > ABM) m = ABM;
  int tid = threadIdx.x;
  if (tid < ABM) {
    int e = g_eid[base + ((tid < m) ? tid : 0)];
    es_eid[tid] = e;
    es_src[tid] = src[e];
    es_dst[tid] = dst[e];
    att_sh[tid] = 0.f;
  }
  __syncthreads();
  // gather K rows (float4)
  for (int idx = tid; idx < ABM*(DD/4); idx += 512) {
    int e = idx / (DD/4), p = idx - e*(DD/4);
    ((float4*)(k_sh + e*DD))[p] = ((const float4*)(g_KQVS + (size_t)es_src[e]*DD))[p];
  }
  int tx = tid & 15, ty = tid >> 4;
  const float* Mr = g_M + (size_t)r*DD*DD;
  const float* Qbase = g_KQVS + (size_t)NN*DD;
  for (int jt = 0; jt < 4; jt++) {
    int j0 = jt*64;
    int jcnt = DD - j0; if (jcnt > 64) jcnt = 64;
    __syncthreads();  // protect Msh/q_t from previous iteration's readers
    for (int idx = tid; idx < DD*16; idx += 512) {
      int i = idx >> 4, p = idx & 15;
      if (p*4 < jcnt)
        *(float4*)(Msh + i*64 + p*4) = *(const float4*)(Mr + (size_t)i*DD + j0 + p*4);
    }
    for (int idx = tid; idx < ABM*16; idx += 512) {
      int e = idx >> 4, p = idx & 15;
      float4 val = make_float4(0.f,0.f,0.f,0.f);  // zero-pad -> stale Msh cols contribute 0
      if (p*4 < jcnt)
        val = *(const float4*)(Qbase + (size_t)es_dst[e]*DD + j0 + p*4);
      *(float4*)(q_t + e*64 + p*4) = val;
    }
    __syncthreads();
    float acc[4][4];
    #pragma unroll
    for (int u=0;u<4;u++) { acc[u][0]=0.f; acc[u][1]=0.f; acc[u][2]=0.f; acc[u][3]=0.f; }
    #pragma unroll 2
    for (int kk = 0; kk < DD; kk++) {
      float4 b = *(const float4*)(Msh + kk*64 + tx*4);
      #pragma unroll
      for (int u=0;u<4;u++) {
        float a = k_sh[(ty*4+u)*DD + kk];
        acc[u][0] = fmaf(a, b.x, acc[u][0]);
        acc[u][1] = fmaf(a, b.y, acc[u][1]);
        acc[u][2] = fmaf(a, b.z, acc[u][2]);
        acc[u][3] = fmaf(a, b.w, acc[u][3]);
      }
    }
    #pragma unroll
    for (int u=0;u<4;u++) {
      float4 qv = *(const float4*)(q_t + (ty*4+u)*64 + tx*4);
      float p = acc[u][0]*qv.x + acc[u][1]*qv.y + acc[u][2]*qv.z + acc[u][3]*qv.w;
      p += __shfl_xor_sync(0xffffffffu, p, 1);
      p += __shfl_xor_sync(0xffffffffu, p, 2);
      p += __shfl_xor_sync(0xffffffffu, p, 4);
      p += __shfl_xor_sync(0xffffffffu, p, 8);
      if (tx == 0) att_sh[ty*4+u] += p;   // unique row per (warp-half) -> no race
    }
  }
  __syncthreads();
  if (tid < m) g_att[es_eid[tid]] = att_sh[tid];
}

// ---------------- segment softmax ----------------
__device__ __forceinline__ unsigned encf(float f) {
  unsigned u = __float_as_uint(f);
  return (u & 0x80000000u) ? ~u : (u | 0x80000000u);
}
__device__ __forceinline__ float decf(unsigned u) {
  return (u & 0x80000000u) ? __uint_as_float(u ^ 0x80000000u) : __uint_as_float(~u);
}
__global__ void k_segmax(const int* __restrict__ dst) {
  int e = blockIdx.x*blockDim.x + threadIdx.x;
  if (e < EE) atomicMax(&g_maxu[dst[e]], encf(g_att[e]));
}
__global__ void k_exp(const int* __restrict__ dst) {
  int e = blockIdx.x*blockDim.x + threadIdx.x;
  if (e < EE) {
    int d = dst[e];
    float ex = expf(g_att[e] - decf(g_maxu[d]));
    g_ex[e] = ex;
    atomicAdd(&g_denom[d], ex);
  }
}
__global__ void k_wts(const int* __restrict__ dst) {
  int e = blockIdx.x*blockDim.x + threadIdx.x;
  if (e < EE) g_ex[e] = g_ex[e] / fmaxf(g_denom[dst[e]], 1e-30f);
}
__global__ void k_agg(const int* __restrict__ src, const int* __restrict__ dst) {
  int idx = blockIdx.x*blockDim.x + threadIdx.x;
  if (idx >= EE*(DD/4)) return;
  int e = idx / (DD/4);
  int p = idx - e*(DD/4);
  float w = g_ex[e];
  float4 v = *(const float4*)(g_KQVS + 2u*NN*DD + (size_t)src[e]*DD + p*4);
  float* o = g_agg + (size_t)dst[e]*DD + p*4;
  atomicAdd(o+0, w*v.x);
  atomicAdd(o+1, w*v.y);
  atomicAdd(o+2, w*v.z);
  atomicAdd(o+3, w*v.w);
}

// ---------------- merge + batchnorm stats ----------------
__global__ void k_combine() {
  __shared__ float cs[DD], cs2[DD];
  int tid = threadIdx.x;
  if (tid < DD) { cs[tid]=0.f; cs2[tid]=0.f; }
  __syncthreads();
  int r0 = blockIdx.x*128;
  for (int idx = tid; idx < 128*DD; idx += blockDim.x) {
    int r = r0 + idx/DD; int c = idx - (idx/DD)*DD;
    if (r < NN) {
      size_t off = (size_t)r*DD + c;
      float val = (g_KQVS[3u*NN*DD + off] + g_agg[off]) * (1.f/3.f);
      g_agg[off] = val;
      atomicAdd(&cs[c], val);
      atomicAdd(&cs2[c], val*val);
    }
  }
  __syncthreads();
  if (tid < DD) { atomicAdd(&g_colsum[tid], cs[tid]); atomicAdd(&g_colsum2[tid], cs2[tid]); }
}
__global__ void k_bnprep(const float* __restrict__ gamma, const float* __restrict__ beta) {
  int c = threadIdx.x;
  if (c < DD) {
    float mean = g_colsum[c] * (1.f/NN);
    float var  = g_colsum2[c] * (1.f/NN) - mean*mean;
    float sc = gamma[c] * rsqrtf(var + 1e-5f);
    g_scale[c] = sc;
    g_shift[c] = beta[c] - mean*sc;
  }
}
__global__ void k_bnout(float* __restrict__ out) {
  int idx = blockIdx.x*blockDim.x + threadIdx.x;
  if (idx < NN*DD) {
    int c = idx - (idx/DD)*DD;
    out[idx] = tanhf(g_agg[idx]*g_scale[c] + g_shift[c]);
  }
}

// ---------------- r_out = r_feats @ wR^T + b ----------------
__global__ void k_rout(const float* __restrict__ rf, const float* __restrict__ wr,
                       const float* __restrict__ br, float* __restrict__ out) {
  __shared__ float xs[DD];
  int r = blockIdx.x;
  int tid = threadIdx.x;
  if (tid < DD) xs[tid] = rf[(size_t)r*DD + tid];
  __syncthreads();
  if (tid < DD) {
    float acc = br[tid];
    const float* wrow = wr + (size_t)tid*DD;
    for (int i = 0; i < DD; i++) acc = fmaf(xs[i], wrow[i], acc);
    out[(size_t)r*DD + tid] = acc;
  }
}

// ---------------- launcher ----------------
extern "C" void kernel_launch(void* const* d_in, const int* in_sizes, int n_in,
                              void* d_out, int out_size) {
  const float* n_in_feats = (const float*)d_in[0];
  const float* r_feats    = (const float*)d_in[1];
  const float* loop_rel   = (const float*)d_in[3];
  const float* rel_att    = (const float*)d_in[4];
  const float* w_comp     = (const float*)d_in[5];
  const float* wS_w = (const float*)d_in[10]; const float* wS_b = (const float*)d_in[11];
  const float* wR_w = (const float*)d_in[12]; const float* wR_b = (const float*)d_in[13];
  const float* k_w  = (const float*)d_in[14]; const float* k_b  = (const float*)d_in[15];
  const float* q_w  = (const float*)d_in[16]; const float* q_b  = (const float*)d_in[17];
  const float* v_w  = (const float*)d_in[18]; const float* v_b  = (const float*)d_in[19];
  const float* gamma = (const float*)d_in[20]; const float* beta = (const float*)d_in[21];
  const int* src   = (const int*)d_in[22];
  const int* dst   = (const int*)d_in[23];
  const int* etype = (const int*)d_in[24];
  float* out = (float*)d_out;

  cudaFuncSetAttribute(k_att, cudaFuncAttributeMaxDynamicSharedMemorySize, ATT_SMEM);

  k_init<<<256, 256>>>();
  k_compM<<<DD, 256>>>(rel_att, w_comp);
  k_pack<<<(OUT4*DD + 255)/256, 256>>>(k_w, q_w, v_w, wS_w);
  k_packb<<<1, OUT4>>>(k_b, q_b, v_b, wS_b, loop_rel, wS_w);
  {
    dim3 g((NN + GBM - 1)/GBM, (OUT4 + GBN - 1)/GBN);
    k_gemm<<<g, 512>>>(n_in_feats);
  }
  k_hist<<<(EE+255)/256, 256>>>(etype);
  k_scan<<<1, 32>>>();
  k_scatter<<<(EE+255)/256, 256>>>(etype);
  {
    dim3 g(RR, 16);
    k_att<<<g, 512, ATT_SMEM>>>(src, dst);
  }
  k_segmax<<<(EE+255)/256, 256>>>(dst);
  k_exp<<<(EE+255)/256, 256>>>(dst);
  k_wts<<<(EE+255)/256, 256>>>(dst);
  k_agg<<<(EE*(DD/4) + 255)/256, 256>>>(src, dst);
  k_combine<<<(NN + 127)/128, 256>>>();
  k_bnprep<<<1, 256>>>(gamma, beta);
  k_bnout<<<(NN*DD + 255)/256, 256>>>(out);
  k_rout<<<RR, 256>>>(r_feats, wR_w, wR_b, out + (size_t)NN*DD);
}